// round 8
// baseline (speedup 1.0000x reference)
#include <cuda_runtime.h>
#include <math.h>

#define BB 4
#define CC 64
#define HH 128
#define WW 128
#define DD 256
#define NN 100
#define MAXDET 10
#define HWP (HH*WW)
#define SEG_OFF   0
#define MASK_OFF  (HWP*BB)
#define KEPT_OFF  (MASK_OFF + HWP*BB)
#define VALID_OFF (KEPT_OFF + BB*MAXDET*5)

#define TP 16                    // pixels per tile
#define RS 20                    // act row stride (floats, 16B-aligned rows)
#define NPART 16                 // seg0 partial blocks
#define MAXTILES 723             // ceil(4*10*17*17/16)

// ---------------- device scratch ----------------
__device__ int   g_ibox[BB][MAXDET][4];
__device__ int   g_valid[BB][MAXDET];
__device__ float g_seg0;
__device__ float g_part[NPART][DD];
__device__ int   g_count;
__device__ int   g_list[BB*HWP];

typedef unsigned long long ull;

__device__ __forceinline__ ull fma2(ull a, ull b, ull c) {
    ull d;
    asm("fma.rn.f32x2 %0, %1, %2, %3;" : "=l"(d) : "l"(a), "l"(b), "l"(c));
    return d;
}
__device__ __forceinline__ ull pack2(float x) {
    unsigned u = __float_as_uint(x);
    ull r;
    asm("mov.b64 %0, {%1, %2};" : "=l"(r) : "r"(u), "r"(u));
    return r;
}
__device__ __forceinline__ void unpack2(ull v, float& lo, float& hi) {
    unsigned a, b;
    asm("mov.b64 {%0, %1}, %2;" : "=r"(a), "=r"(b) : "l"(v));
    lo = __uint_as_float(a);
    hi = __uint_as_float(b);
}

// ---------------- Kernel 1: NMS (blocks 0-3) + seg0 partials ------------
__global__ void __launch_bounds__(256) front_kernel(
        const float* __restrict__ rb,
        const float* __restrict__ b1v, const float* __restrict__ W2,
        float* __restrict__ out) {
    const int t = threadIdx.x;

    if (blockIdx.x >= BB) {
        const int blk = blockIdx.x - BB;
        const int d0 = blk * 16;
        float h1[16];
        #pragma unroll
        for (int j = 0; j < 16; j++) h1[j] = fmaxf(__ldg(&b1v[d0 + j]), 0.f);
        float acc = 0.f;
        #pragma unroll
        for (int j = 0; j < 16; j++) acc += h1[j] * __ldg(&W2[(d0 + j)*DD + t]);
        g_part[blk][t] = acc;
        return;
    }

    const int b = blockIdx.x;
    __shared__ float bx[NN*5];
    __shared__ float area[NN];
    __shared__ float iou[NN*NN];
    __shared__ int   s_any;
    __shared__ int   idxs[MAXDET];
    __shared__ int   hasA[MAXDET];

    for (int i = t; i < NN*5; i += 256) bx[i] = rb[b*NN*5 + i];
    if (t == 0) s_any = 0;
    __syncthreads();

    if (t < NN) {
        float a = fmaxf(bx[t*5+2]-bx[t*5+0], 0.f) * fmaxf(bx[t*5+3]-bx[t*5+1], 0.f);
        area[t] = a;
        if (bx[t*5+4] > 0.2f) atomicOr(&s_any, 1);
    }
    __syncthreads();

    for (int k = t; k < NN*NN; k += 256) {
        int i = k / NN, j = k - i*NN;
        float lx = fmaxf(bx[i*5+0], bx[j*5+0]);
        float ly = fmaxf(bx[i*5+1], bx[j*5+1]);
        float rx = fminf(bx[i*5+2], bx[j*5+2]);
        float ry = fminf(bx[i*5+3], bx[j*5+3]);
        float iw = fmaxf(rx - lx, 0.f);
        float ih = fmaxf(ry - ly, 0.f);
        float inter = iw * ih;
        iou[k] = inter / (area[i] + area[j] - inter + 1e-9f);
    }
    __syncthreads();

    if (t < 32) {
        const int l = t;
        const int anyv = s_any;
        float cf[4];
        int   act[4];
        #pragma unroll
        for (int m = 0; m < 4; m++) {
            int c = l + 32*m;
            bool ok = c < NN;
            cf[m]  = ok ? bx[c*5+4] : -INFINITY;
            act[m] = ok ? (anyv ? (cf[m] > 0.2f ? 1 : 0) : 1) : 0;
        }
        for (int it = 0; it < MAXDET; it++) {
            float bv = -INFINITY;
            int   bi = l;
            #pragma unroll
            for (int m = 0; m < 4; m++) {
                int c = l + 32*m;
                if (act[m] && cf[m] > bv) { bv = cf[m]; bi = c; }
            }
            #pragma unroll
            for (int off = 16; off; off >>= 1) {
                float v2 = __shfl_xor_sync(0xffffffffu, bv, off);
                int   i2 = __shfl_xor_sync(0xffffffffu, bi, off);
                if (v2 > bv || (v2 == bv && i2 < bi)) { bv = v2; bi = i2; }
            }
            bool has = bv > -INFINITY;
            if (l == 0) { idxs[it] = bi; hasA[it] = has ? 1 : 0; }
            if (has) {
                #pragma unroll
                for (int m = 0; m < 4; m++) {
                    int c = l + 32*m;
                    if (act[m] && (c == bi || iou[bi*NN + c] > 0.4f)) act[m] = 0;
                }
            }
        }
    }
    __syncthreads();

    if (t < MAXDET*5) {
        int det = t / 5, k = t - det*5;
        out[KEPT_OFF + b*MAXDET*5 + t] = bx[idxs[det]*5 + k];
    }
    if (t < MAXDET) {
        int kr = idxs[t];
        float x1f = bx[kr*5+0], y1f = bx[kr*5+1];
        float x2f = bx[kr*5+2], y2f = bx[kr*5+3];
        int v = hasA[t] && (x2f - x1f >= 1.f) && (y2f - y1f >= 1.f)
                        && (s_any ? 1 : (t < 5));
        out[VALID_OFF + b*MAXDET + t] = v ? 1.f : 0.f;
        g_valid[b][t] = v;
        int x1 = (int)floorf(x1f + 0.5f); x1 = min(max(x1, 0), WW);
        int y1 = (int)floorf(y1f + 0.5f); y1 = min(max(y1, 0), HH);
        int x2 = (int)floorf(x2f + 0.5f); x2 = min(max(x2, 0), WW);
        int y2 = (int)floorf(y2f + 0.5f); y2 = min(max(y2, 0), HH);
        g_ibox[b][t][0] = x1; g_ibox[b][t][1] = y1;
        g_ibox[b][t][2] = x2; g_ibox[b][t][3] = y2;
    }
}

// ---------------- Kernel 2: combine seg0 partials ----------------
__global__ void __launch_bounds__(256) combine_kernel(
        const float* __restrict__ b2v, const float* __restrict__ W3,
        const float* __restrict__ b3v) {
    __shared__ float red[256];
    const int t = threadIdx.x;
    float acc = b2v[t];
    #pragma unroll
    for (int blk = 0; blk < NPART; blk++) acc += g_part[blk][t];
    red[t] = fmaxf(acc, 0.f) * W3[t];
    __syncthreads();
    for (int off = 128; off; off >>= 1) {
        if (t < off) red[t] += red[t + off];
        __syncthreads();
    }
    if (t == 0) { g_seg0 = red[0] + b3v[0]; g_count = 0; }
}

// ---------------- Kernel 3: mask + default seg + compact ----------------
__global__ void mask_kernel(float* __restrict__ out) {
    int p = blockIdx.x * blockDim.x + threadIdx.x;
    if (p >= HWP) return;
    int h = p >> 7;
    int w = p & (WW - 1);
    float s0 = g_seg0;
    *(float4*)&out[SEG_OFF + p*BB] = make_float4(s0, s0, s0, s0);
    #pragma unroll
    for (int b = 0; b < BB; b++) {
        bool inside = false;
        #pragma unroll
        for (int k = 0; k < MAXDET; k++) {
            if (g_valid[b][k]) {
                inside |= (w >= g_ibox[b][k][0] && w < g_ibox[b][k][2] &&
                           h >= g_ibox[b][k][1] && h < g_ibox[b][k][3]);
            }
        }
        out[MASK_OFF + b*HWP + p] = inside ? 0.f : 1.f;
        if (inside) {
            int pos = atomicAdd(&g_count, 1);
            g_list[pos] = (b << 14) | p;
        }
    }
}

// ---------------- MLP layer: thread = 2 feats x 16 px, 2-way k-split ------
// Partials of kp==1 staged IN-PLACE in dst rows; kp==0 combines.
template<int K, bool RELU, bool FINAL>
__device__ __forceinline__ void layerT(
        const float* __restrict__ Wm, const float* __restrict__ bias,
        const float* __restrict__ W3v,
        const float (*in)[RS], float (*dst)[RS],
        int f0, int kp, float* sp) {
    ull acc[2][8];
    #pragma unroll
    for (int j = 0; j < 2; j++)
        #pragma unroll
        for (int pp = 0; pp < 8; pp++) acc[j][pp] = 0;

    const int kh = K >> 1;
    const float* a = &in[kp * kh][0];
    const float* w = &Wm[(size_t)(kp * kh) * DD + f0];
    #pragma unroll 4
    for (int i = 0; i < kh; i++) {
        float2 wf = *(const float2*)w;
        ull w0 = pack2(wf.x), w1 = pack2(wf.y);
        ulonglong2 r0 = *(const ulonglong2*)(a + 0);
        ulonglong2 r1 = *(const ulonglong2*)(a + 4);
        ulonglong2 r2 = *(const ulonglong2*)(a + 8);
        ulonglong2 r3 = *(const ulonglong2*)(a + 12);
        acc[0][0] = fma2(w0, r0.x, acc[0][0]);
        acc[0][1] = fma2(w0, r0.y, acc[0][1]);
        acc[0][2] = fma2(w0, r1.x, acc[0][2]);
        acc[0][3] = fma2(w0, r1.y, acc[0][3]);
        acc[0][4] = fma2(w0, r2.x, acc[0][4]);
        acc[0][5] = fma2(w0, r2.y, acc[0][5]);
        acc[0][6] = fma2(w0, r3.x, acc[0][6]);
        acc[0][7] = fma2(w0, r3.y, acc[0][7]);
        acc[1][0] = fma2(w1, r0.x, acc[1][0]);
        acc[1][1] = fma2(w1, r0.y, acc[1][1]);
        acc[1][2] = fma2(w1, r1.x, acc[1][2]);
        acc[1][3] = fma2(w1, r1.y, acc[1][3]);
        acc[1][4] = fma2(w1, r2.x, acc[1][4]);
        acc[1][5] = fma2(w1, r2.y, acc[1][5]);
        acc[1][6] = fma2(w1, r3.x, acc[1][6]);
        acc[1][7] = fma2(w1, r3.y, acc[1][7]);
        a += RS;
        w += DD;
    }

    if (kp) {
        #pragma unroll
        for (int j = 0; j < 2; j++) {
            float v[16];
            #pragma unroll
            for (int pp = 0; pp < 8; pp++) unpack2(acc[j][pp], v[2*pp], v[2*pp+1]);
            float* row = &dst[f0 + j][0];
            *(float4*)&row[0]  = make_float4(v[0],  v[1],  v[2],  v[3]);
            *(float4*)&row[4]  = make_float4(v[4],  v[5],  v[6],  v[7]);
            *(float4*)&row[8]  = make_float4(v[8],  v[9],  v[10], v[11]);
            *(float4*)&row[12] = make_float4(v[12], v[13], v[14], v[15]);
        }
    }
    __syncthreads();
    if (!kp) {
        float2 bb = *(const float2*)&bias[f0];
        float2 w3f = make_float2(0.f, 0.f);
        if (FINAL) w3f = *(const float2*)&W3v[f0];
        #pragma unroll
        for (int j = 0; j < 2; j++) {
            float v[16];
            #pragma unroll
            for (int pp = 0; pp < 8; pp++) unpack2(acc[j][pp], v[2*pp], v[2*pp+1]);
            float bj = j ? bb.y : bb.x;
            float* row = &dst[f0 + j][0];
            float4 q0 = *(const float4*)&row[0];
            float4 q1 = *(const float4*)&row[4];
            float4 q2 = *(const float4*)&row[8];
            float4 q3 = *(const float4*)&row[12];
            v[0]  += bj + q0.x; v[1]  += bj + q0.y; v[2]  += bj + q0.z; v[3]  += bj + q0.w;
            v[4]  += bj + q1.x; v[5]  += bj + q1.y; v[6]  += bj + q1.z; v[7]  += bj + q1.w;
            v[8]  += bj + q2.x; v[9]  += bj + q2.y; v[10] += bj + q2.z; v[11] += bj + q2.w;
            v[12] += bj + q3.x; v[13] += bj + q3.y; v[14] += bj + q3.z; v[15] += bj + q3.w;
            if (RELU) {
                #pragma unroll
                for (int i = 0; i < 16; i++) v[i] = fmaxf(v[i], 0.f);
            }
            if (FINAL) {
                float w3j = j ? w3f.y : w3f.x;
                #pragma unroll
                for (int i = 0; i < 16; i++) sp[i] += v[i] * w3j;
            } else {
                *(float4*)&row[0]  = make_float4(v[0],  v[1],  v[2],  v[3]);
                *(float4*)&row[4]  = make_float4(v[4],  v[5],  v[6],  v[7]);
                *(float4*)&row[8]  = make_float4(v[8],  v[9],  v[10], v[11]);
                *(float4*)&row[12] = make_float4(v[12], v[13], v[14], v[15]);
            }
        }
    }
    __syncthreads();
}

// ---------------- Kernel 4: compacted-tile MLP, 256 thr ----------------
__global__ void __launch_bounds__(256, 4) mlp_kernel(
        const float* __restrict__ x,
        const float* __restrict__ W_sem, const float* __restrict__ b_sem,
        const float* __restrict__ W1, const float* __restrict__ b1,
        const float* __restrict__ W2, const float* __restrict__ b2,
        const float* __restrict__ W3, const float* __restrict__ b3,
        float* __restrict__ out) {
    __shared__ __align__(16) float sx[CC][RS];
    __shared__ __align__(16) float sA[DD][RS];
    __shared__ __align__(16) float sB[DD][RS];
    __shared__ int spix[TP];

    const int count  = g_count;
    const int ntiles = (count + TP - 1) / TP;
    if (blockIdx.x >= ntiles) return;
    const int base = blockIdx.x * TP;
    const int rem  = min(count - base, TP);

    const int tid = threadIdx.x;     // 256
    const int kp  = tid >> 7;        // k half
    const int fp  = tid & 127;       // feature pair
    const int f0  = fp * 2;

    if (tid < TP) spix[tid] = g_list[tid < rem ? base + tid : base];
    __syncthreads();

    for (int i = tid; i < CC*TP; i += 256) {
        int c = i >> 4, p = i & (TP - 1);
        int gid = spix[p];
        sx[c][p] = x[(((gid >> 14) << 6) + c) * HWP + (gid & (HWP - 1))];
    }
    __syncthreads();

    float sp[16];
    #pragma unroll
    for (int i = 0; i < 16; i++) sp[i] = 0.f;

    layerT<CC, false, false>(W_sem, b_sem, nullptr, sx, sA, f0, kp, sp);
    layerT<DD, true,  false>(W1,    b1,    nullptr, sA, sB, f0, kp, sp);
    layerT<DD, true,  true >(W2,    b2,    W3,      sB, sA, f0, kp, sp);

    // kp0 threads hold per-fp partial dots for all 16 px; stage in sA rows 0..127
    if (!kp) {
        float* row = &sA[fp][0];
        *(float4*)&row[0]  = make_float4(sp[0],  sp[1],  sp[2],  sp[3]);
        *(float4*)&row[4]  = make_float4(sp[4],  sp[5],  sp[6],  sp[7]);
        *(float4*)&row[8]  = make_float4(sp[8],  sp[9],  sp[10], sp[11]);
        *(float4*)&row[12] = make_float4(sp[12], sp[13], sp[14], sp[15]);
    }
    __syncthreads();

    // warp w reduces pixels 2w, 2w+1 over 128 fp rows
    const int warp = tid >> 5;
    const int l    = tid & 31;
    {
        int p0 = warp * 2, p1 = warp * 2 + 1;
        float s0 = sA[l][p0] + sA[l+32][p0] + sA[l+64][p0] + sA[l+96][p0];
        float s1 = sA[l][p1] + sA[l+32][p1] + sA[l+64][p1] + sA[l+96][p1];
        #pragma unroll
        for (int off = 16; off; off >>= 1) {
            s0 += __shfl_xor_sync(0xffffffffu, s0, off);
            s1 += __shfl_xor_sync(0xffffffffu, s1, off);
        }
        if (l == 0) {
            float bb = b3[0];
            if (p0 < rem) {
                int gid = spix[p0];
                out[SEG_OFF + (gid & (HWP-1))*BB + (gid >> 14)] = s0 + bb;
            }
            if (p1 < rem) {
                int gid = spix[p1];
                out[SEG_OFF + (gid & (HWP-1))*BB + (gid >> 14)] = s1 + bb;
            }
        }
    }
}

// ---------------- launch ----------------
extern "C" void kernel_launch(void* const* d_in, const int* in_sizes, int n_in,
                              void* d_out, int out_size) {
    (void)in_sizes; (void)n_in; (void)out_size;
    const float* x     = (const float*)d_in[0];
    const float* rb    = (const float*)d_in[1];
    const float* W_sem = (const float*)d_in[2];
    const float* b_sem = (const float*)d_in[3];
    const float* W1    = (const float*)d_in[4];
    const float* b1    = (const float*)d_in[5];
    const float* W2    = (const float*)d_in[6];
    const float* b2    = (const float*)d_in[7];
    const float* W3    = (const float*)d_in[8];
    const float* b3    = (const float*)d_in[9];
    float* out = (float*)d_out;

    front_kernel<<<BB + NPART, 256>>>(rb, b1, W2, out);
    combine_kernel<<<1, 256>>>(b2, W3, b3);
    mask_kernel<<<HWP/256, 256>>>(out);
    mlp_kernel<<<MAXTILES, 256>>>(x, W_sem, b_sem, W1, b1, W2, b2, W3, b3, out);
}